// round 8
// baseline (speedup 1.0000x reference)
#include <cuda_runtime.h>
#include <cuda_fp16.h>
#include <mma.h>
#include <cstdint>

using namespace nvcuda;

#define N_NODES 100000
#define N_PAD   100096   // 782 * 128
#define N_EDGES 3200000
#define H 128
#define HQ 256
#define A_DIM 10
#define NBLK_SCAN 98
#define N_CHUNK 4
// tile (128-row) counts per chunk: 196+196+196+194 = 782
static const int CH_TILES[N_CHUNK] = {196, 196, 196, 194};
static const int CH_TILE_BASE[N_CHUNK] = {0, 196, 392, 588};

static inline int cdiv(int a, int b) { return (a + b - 1) / b; }

// ---------------- scratch ----------------
__device__ __half g_xw16[(size_t)N_PAD * H];  // fp16 relu(x@We+be)@Wg (UNscaled)
__device__ __half g_h216[(size_t)N_PAD * H];  // fp16 relu(gcn agg); pad rows stay 0
__device__ __half g_W116[HQ * H];             // fp16 W1 [128,256]
__device__ __half g_Wg16[H * H];              // fp16 W_gcn [128,128]
__device__ float  g_dinv[N_NODES];
__device__ int    g_deg[N_NODES];
__device__ int    g_rowptr[N_NODES + 1];
__device__ int    g_cursor[N_NODES];
__device__ int    g_csrc[N_EDGES];
__device__ int    g_dst32[N_EDGES];
__device__ int    g_is32;
__device__ int    g_bsum[NBLK_SCAN];
__device__ int    g_boff[NBLK_SCAN];

// ---------------- cp.async helpers ----------------
__device__ __forceinline__ void cp16(void* s, const void* g, bool p) {
    uint32_t sa = (uint32_t)__cvta_generic_to_shared(s);
    int sz = p ? 16 : 0;
    asm volatile("cp.async.cg.shared.global [%0], [%1], 16, %2;\n"
                 :: "r"(sa), "l"(g), "r"(sz));
}
__device__ __forceinline__ void cp_commit() {
    asm volatile("cp.async.commit_group;\n");
}
template <int NN>
__device__ __forceinline__ void cp_wait() {
    asm volatile("cp.async.wait_group %0;\n" :: "n"(NN));
}

// ---------------- generic fp32 -> fp16 convert ----------------
__global__ void k_cvt16(const float* __restrict__ src, __half* __restrict__ dst, int n4) {
    int i = blockIdx.x * blockDim.x + threadIdx.x;
    if (i >= n4) return;
    float4 v = *(const float4*)&src[i * 4];
    __half2 h0 = __floats2half2_rn(v.x, v.y);
    __half2 h1 = __floats2half2_rn(v.z, v.w);
    uint2 u;
    u.x = *(uint32_t*)&h0;
    u.y = *(uint32_t*)&h1;
    *(uint2*)&dst[i * 4] = u;
}

// ---------------- edge dtype detect ----------------
__global__ void k_detect(const void* ei) {
    if (threadIdx.x == 0 && blockIdx.x == 0) {
        const long long* p = (const long long*)ei;
        int is32 = 0;
        for (int i = 0; i < 64; i++) {
            long long v = p[i];
            if (v < 0 || v >= (long long)N_NODES) { is32 = 1; break; }
        }
        g_is32 = is32;
    }
}

__global__ void k_zero_deg() {
    int i = blockIdx.x * blockDim.x + threadIdx.x;
    if (i < N_NODES) g_deg[i] = 0;
}

// histogram over dst half only; cache dst as int32
__global__ void k_hist(const void* ei) {
    int i = blockIdx.x * blockDim.x + threadIdx.x;   // 2 edges/thread
    int base = i * 2;
    if (base >= N_EDGES) return;
    int v0, v1;
    if (g_is32) {
        int2 p = ((const int2*)ei)[N_EDGES / 2 + i];
        v0 = p.x; v1 = p.y;
    } else {
        longlong2 p = ((const longlong2*)ei)[N_EDGES / 2 + i];
        v0 = (int)p.x; v1 = (int)p.y;
    }
    *(int2*)&g_dst32[base] = make_int2(v0, v1);
    atomicAdd(&g_deg[v0], 1);
    atomicAdd(&g_deg[v1], 1);
}

// ---------- 3-phase scan ----------
__global__ void k_scan1() {
    __shared__ int warpsum[32];
    int tid = threadIdx.x, lane = tid & 31, wid = tid >> 5;
    int i = blockIdx.x * 1024 + tid;
    int v = (i < N_NODES) ? g_deg[i] : 0;
    int x = v;
#pragma unroll
    for (int off = 1; off < 32; off <<= 1) {
        int y = __shfl_up_sync(0xffffffffu, x, off);
        if (lane >= off) x += y;
    }
    if (lane == 31) warpsum[wid] = x;
    __syncthreads();
    if (wid == 0) {
        int w = warpsum[lane];
#pragma unroll
        for (int off = 1; off < 32; off <<= 1) {
            int y = __shfl_up_sync(0xffffffffu, w, off);
            if (lane >= off) w += y;
        }
        warpsum[lane] = w;
    }
    __syncthreads();
    int incl = x + (wid > 0 ? warpsum[wid - 1] : 0);
    if (i < N_NODES) {
        g_rowptr[i] = incl - v;
        g_dinv[i] = rsqrtf((float)(v + 1));
    }
    if (tid == 1023) g_bsum[blockIdx.x] = incl;
}

__global__ void k_scan2() {
    __shared__ int s[128];
    int t = threadIdx.x;
    s[t] = (t < NBLK_SCAN) ? g_bsum[t] : 0;
    __syncthreads();
    for (int off = 1; off < 128; off <<= 1) {
        int v = (t >= off) ? s[t - off] : 0;
        __syncthreads();
        s[t] += v;
        __syncthreads();
    }
    if (t < NBLK_SCAN) g_boff[t] = (t > 0) ? s[t - 1] : 0;
    if (t == 0) g_rowptr[N_NODES] = s[NBLK_SCAN - 1];
}

__global__ void k_scan3() {
    int i = blockIdx.x * 1024 + threadIdx.x;
    if (i >= N_NODES) return;
    int r = g_rowptr[i] + g_boff[blockIdx.x];
    g_rowptr[i] = r;
    g_cursor[i] = r;
}

// fill CSR: src read straight from edge_index
__global__ void k_fill(const void* ei) {
    int i = blockIdx.x * blockDim.x + threadIdx.x;   // 4 edges/thread
    int base = i * 4;
    if (base >= N_EDGES) return;
    int s0, s1, s2, s3;
    if (g_is32) {
        int4 sv = ((const int4*)ei)[i];
        s0 = sv.x; s1 = sv.y; s2 = sv.z; s3 = sv.w;
    } else {
        longlong2 a = ((const longlong2*)ei)[i * 2];
        longlong2 b = ((const longlong2*)ei)[i * 2 + 1];
        s0 = (int)a.x; s1 = (int)a.y; s2 = (int)b.x; s3 = (int)b.y;
    }
    int4 d = *(const int4*)&g_dst32[base];
    g_csrc[atomicAdd(&g_cursor[d.x], 1)] = s0;
    g_csrc[atomicAdd(&g_cursor[d.y], 1)] = s1;
    g_csrc[atomicAdd(&g_cursor[d.z], 1)] = s2;
    g_csrc[atomicAdd(&g_cursor[d.w], 1)] = s3;
}

// ================= fused encoder + GCN-weight GEMM =================
// stage 1 (tf32): h1 = x @ W_enc ; stage 2 (fp16): xw = relu(h1+b) @ W_gcn
#define LDA 36        // floats
#define LDW 132       // floats
#define LDH 136       // halves

__global__ __launch_bounds__(256) void k_enc(
    const float* __restrict__ x, const float* __restrict__ W_enc,
    const float* __restrict__ b_enc)
{
    extern __shared__ float pool[];
    float*  xs = pool;
    float*  Ws = pool + 9216;
    float*  Hs = pool + 26112;
    __half* Hh = (__half*)pool;
    __half* Wh = (__half*)(pool + 9216);
    __shared__ float sbe[128];

    const int tid = threadIdx.x;
    const int wid = tid >> 5;
    const int wm = wid & 3, wn = wid >> 2;
    const int rowBase = blockIdx.x * 128;

    if (tid < 128) sbe[tid] = b_enc[tid];

#pragma unroll
    for (int i = 0; i < 16; i++) {
        int slot = tid + i * 256;
        int r = slot >> 5, c4 = (slot & 31) * 4;
        *(float4*)&Ws[r * LDW + c4] = *(const float4*)&W_enc[r * 128 + c4];
    }

    auto stageA = [&](int buf, int kt) {
        float* dst = xs + buf * (128 * LDA);
#pragma unroll
        for (int i = 0; i < 4; i++) {
            int slot = tid + i * 256;
            int r = slot >> 3, c4 = (slot & 7) * 4;
            int gr = rowBase + r;
            cp16(&dst[r * LDA + c4], &x[(size_t)gr * 128 + kt + c4], gr < N_NODES);
        }
        cp_commit();
    };

    wmma::fragment<wmma::accumulator, 16, 16, 8, float> acc1[2][4];
#pragma unroll
    for (int mt = 0; mt < 2; mt++)
#pragma unroll
        for (int nt = 0; nt < 4; nt++) wmma::fill_fragment(acc1[mt][nt], 0.f);

    stageA(0, 0);
    for (int c = 0; c < 4; c++) {
        if (c < 3) { stageA((c + 1) & 1, (c + 1) * 32); cp_wait<1>(); }
        else       cp_wait<0>();
        __syncthreads();
        float* cur = xs + (c & 1) * (128 * LDA);
#pragma unroll
        for (int ks = 0; ks < 4; ks++) {
            int k = ks * 8, kg = c * 32 + k;
            wmma::fragment<wmma::matrix_a, 16, 16, 8, wmma::precision::tf32, wmma::row_major> af[2];
            wmma::fragment<wmma::matrix_b, 16, 16, 8, wmma::precision::tf32, wmma::row_major> bf[4];
#pragma unroll
            for (int mt = 0; mt < 2; mt++) {
                wmma::load_matrix_sync(af[mt], &cur[(wm * 32 + mt * 16) * LDA + k], LDA);
#pragma unroll
                for (int e = 0; e < af[mt].num_elements; e++)
                    af[mt].x[e] = wmma::__float_to_tf32(af[mt].x[e]);
            }
#pragma unroll
            for (int nt = 0; nt < 4; nt++) {
                wmma::load_matrix_sync(bf[nt], &Ws[kg * LDW + wn * 64 + nt * 16], LDW);
#pragma unroll
                for (int e = 0; e < bf[nt].num_elements; e++)
                    bf[nt].x[e] = wmma::__float_to_tf32(bf[nt].x[e]);
            }
#pragma unroll
            for (int mt = 0; mt < 2; mt++)
#pragma unroll
                for (int nt = 0; nt < 4; nt++)
                    wmma::mma_sync(acc1[mt][nt], af[mt], bf[nt], acc1[mt][nt]);
        }
        __syncthreads();
    }

#pragma unroll
    for (int mt = 0; mt < 2; mt++)
#pragma unroll
        for (int nt = 0; nt < 4; nt++)
            wmma::store_matrix_sync(&Hs[(wm * 32 + mt * 16) * LDW + wn * 64 + nt * 16],
                                    acc1[mt][nt], LDW, wmma::mem_row_major);
#pragma unroll
    for (int i = 0; i < 8; i++) {
        int slot = tid + i * 256;
        int r = slot >> 4, c8 = (slot & 15) * 8;
        *(uint4*)&Wh[r * LDH + c8] = *(const uint4*)&g_Wg16[r * 128 + c8];
    }
    __syncthreads();

#pragma unroll
    for (int i = 0; i < 16; i++) {
        int slot = tid + i * 256;
        int r = slot >> 5, c4 = (slot & 31) * 4;
        float4 v = *(float4*)&Hs[r * LDW + c4];
        __half2 h0 = __floats2half2_rn(fmaxf(v.x + sbe[c4 + 0], 0.f),
                                       fmaxf(v.y + sbe[c4 + 1], 0.f));
        __half2 h1 = __floats2half2_rn(fmaxf(v.z + sbe[c4 + 2], 0.f),
                                       fmaxf(v.w + sbe[c4 + 3], 0.f));
        uint2 u;
        u.x = *(uint32_t*)&h0;
        u.y = *(uint32_t*)&h1;
        *(uint2*)&Hh[r * LDH + c4] = u;
    }
    __syncthreads();

    wmma::fragment<wmma::accumulator, 16, 16, 16, float> acc2[2][4];
#pragma unroll
    for (int mt = 0; mt < 2; mt++)
#pragma unroll
        for (int nt = 0; nt < 4; nt++) wmma::fill_fragment(acc2[mt][nt], 0.f);

#pragma unroll
    for (int ks = 0; ks < 8; ks++) {
        int k = ks * 16;
        wmma::fragment<wmma::matrix_a, 16, 16, 16, __half, wmma::row_major> af[2];
        wmma::fragment<wmma::matrix_b, 16, 16, 16, __half, wmma::row_major> bf[4];
#pragma unroll
        for (int mt = 0; mt < 2; mt++)
            wmma::load_matrix_sync(af[mt], &Hh[(wm * 32 + mt * 16) * LDH + k], LDH);
#pragma unroll
        for (int nt = 0; nt < 4; nt++)
            wmma::load_matrix_sync(bf[nt], &Wh[k * LDH + wn * 64 + nt * 16], LDH);
#pragma unroll
        for (int mt = 0; mt < 2; mt++)
#pragma unroll
            for (int nt = 0; nt < 4; nt++)
                wmma::mma_sync(acc2[mt][nt], af[mt], bf[nt], acc2[mt][nt]);
    }
    __syncthreads();

#pragma unroll
    for (int mt = 0; mt < 2; mt++)
#pragma unroll
        for (int nt = 0; nt < 4; nt++)
            wmma::store_matrix_sync(&Hs[(wm * 32 + mt * 16) * LDW + wn * 64 + nt * 16],
                                    acc2[mt][nt], LDW, wmma::mem_row_major);
    __syncthreads();

#pragma unroll
    for (int i = 0; i < 16; i++) {
        int slot = tid + i * 256;
        int r = slot >> 5, c4 = (slot & 31) * 4;
        int gr = rowBase + r;
        float4 v = *(float4*)&Hs[r * LDW + c4];
        __half2 h0 = __floats2half2_rn(v.x, v.y);
        __half2 h1 = __floats2half2_rn(v.z, v.w);
        uint2 u;
        u.x = *(uint32_t*)&h0;
        u.y = *(uint32_t*)&h1;
        *(uint2*)&g_xw16[(size_t)gr * 128 + c4] = u;
    }
}

// ------- GCN aggregation: 2 nodes/warp, 16 lanes x 16B per row, chunked -------
__device__ __forceinline__ void fma8(float* acc, float c, uint4 u) {
    __half2* h = (__half2*)&u;
#pragma unroll
    for (int q = 0; q < 4; q++) {
        float2 f = __half22float2(h[q]);
        acc[q * 2]     = fmaf(c, f.x, acc[q * 2]);
        acc[q * 2 + 1] = fmaf(c, f.y, acc[q * 2 + 1]);
    }
}

__global__ void k_agg(const float* __restrict__ b_gcn, int nodeBase, int nodeCount) {
    int warpId = (blockIdx.x * blockDim.x + threadIdx.x) >> 5;
    int lane = threadIdx.x & 31;
    int sub = lane >> 4;
    int l16 = lane & 15;
    unsigned hmask = sub ? 0xFFFF0000u : 0x0000FFFFu;
    int local = warpId * 2 + sub;
    if (local >= nodeCount) return;
    int gw = nodeBase + local;
    if (gw >= N_NODES) return;

    int beg = g_rowptr[gw];
    int end = g_rowptr[gw + 1];

    float acc[8];
#pragma unroll
    for (int q = 0; q < 8; q++) acc[q] = 0.f;

    const int colh = l16 * 8;

    for (int base = beg; base < end; base += 16) {
        int e = base + l16;
        int s = (e < end) ? g_csrc[e] : 0;
        int cnt = min(16, end - base);
        if (cnt == 16) {
#pragma unroll
            for (int j = 0; j < 16; j++) {
                int sj = __shfl_sync(hmask, s, sub * 16 + j);
                float c = g_dinv[sj];
                uint4 u = *(const uint4*)&g_xw16[(size_t)sj * 128 + colh];
                fma8(acc, c, u);
            }
        } else {
            for (int j = 0; j < cnt; j++) {
                int sj = __shfl_sync(hmask, s, sub * 16 + j);
                float c = g_dinv[sj];
                uint4 u = *(const uint4*)&g_xw16[(size_t)sj * 128 + colh];
                fma8(acc, c, u);
            }
        }
    }

    float di = g_dinv[gw];
    {
        uint4 u = *(const uint4*)&g_xw16[(size_t)gw * 128 + colh];
        fma8(acc, di, u);
    }

    float4 b0 = *(const float4*)&b_gcn[colh];
    float4 b1 = *(const float4*)&b_gcn[colh + 4];
    float bb[8] = {b0.x, b0.y, b0.z, b0.w, b1.x, b1.y, b1.z, b1.w};
    __half2 ho[4];
#pragma unroll
    for (int q = 0; q < 4; q++) {
        float ox = fmaxf(fmaf(di, acc[q * 2],     bb[q * 2]),     0.f);
        float oy = fmaxf(fmaf(di, acc[q * 2 + 1], bb[q * 2 + 1]), 0.f);
        ho[q] = __floats2half2_rn(ox, oy);
    }
    *(uint4*)&g_h216[(size_t)gw * 128 + colh] = *(uint4*)ho;
}

// ========== fused MLP head (fp16 wmma, single K stage), chunked ==========
#define LDA2 136     // halves
#define LDB2 264     // halves
#define LDT 264      // floats

__global__ __launch_bounds__(512) void k_w1out(
    const float* __restrict__ b1, const float* __restrict__ W2,
    const float* __restrict__ b2, float* __restrict__ out, int tileBase)
{
    extern __shared__ float pool[];
    __half* As = (__half*)pool;
    __half* Bs = (__half*)pool + 128 * LDA2;
    float*  Ts = pool;
    __shared__ float sW2[HQ * A_DIM];
    __shared__ float sb1[HQ];
    __shared__ float sb2[A_DIM];

    const int tid = threadIdx.x;
    const int wid = tid >> 5, lane = tid & 31;
    const int wm = wid & 3, wn = wid >> 2;
    const int rowBase = (tileBase + blockIdx.x) * 128;

    for (int j = tid; j < HQ * A_DIM; j += 512) sW2[j] = W2[j];
    for (int j = tid; j < HQ; j += 512) sb1[j] = b1[j];
    if (tid < A_DIM) sb2[tid] = b2[tid];

#pragma unroll
    for (int i = 0; i < 4; i++) {
        int slot = tid + i * 512;
        int r = slot >> 4, c8 = (slot & 15) * 8;
        cp16(&As[r * LDA2 + c8], &g_h216[(size_t)(rowBase + r) * 128 + c8], true);
    }
#pragma unroll
    for (int i = 0; i < 8; i++) {
        int slot = tid + i * 512;
        int r = slot >> 5, c8 = (slot & 31) * 8;
        cp16(&Bs[r * LDB2 + c8], &g_W116[(size_t)r * 256 + c8], true);
    }
    cp_commit();
    cp_wait<0>();
    __syncthreads();

    wmma::fragment<wmma::accumulator, 16, 16, 16, float> acc[2][4];
#pragma unroll
    for (int mt = 0; mt < 2; mt++)
#pragma unroll
        for (int nt = 0; nt < 4; nt++) wmma::fill_fragment(acc[mt][nt], 0.f);

#pragma unroll
    for (int ks = 0; ks < 8; ks++) {
        int k = ks * 16;
        wmma::fragment<wmma::matrix_a, 16, 16, 16, __half, wmma::row_major> af[2];
        wmma::fragment<wmma::matrix_b, 16, 16, 16, __half, wmma::row_major> bf[4];
#pragma unroll
        for (int mt = 0; mt < 2; mt++)
            wmma::load_matrix_sync(af[mt], &As[(wm * 32 + mt * 16) * LDA2 + k], LDA2);
#pragma unroll
        for (int nt = 0; nt < 4; nt++)
            wmma::load_matrix_sync(bf[nt], &Bs[k * LDB2 + wn * 64 + nt * 16], LDB2);
#pragma unroll
        for (int mt = 0; mt < 2; mt++)
#pragma unroll
            for (int nt = 0; nt < 4; nt++)
                wmma::mma_sync(acc[mt][nt], af[mt], bf[nt], acc[mt][nt]);
    }
    __syncthreads();

#pragma unroll
    for (int mt = 0; mt < 2; mt++)
#pragma unroll
        for (int nt = 0; nt < 4; nt++)
            wmma::store_matrix_sync(&Ts[(wm * 32 + mt * 16) * LDT + wn * 64 + nt * 16],
                                    acc[mt][nt], LDT, wmma::mem_row_major);
    __syncthreads();

    int r0 = wid * 8;
#pragma unroll
    for (int rr = 0; rr < 8; rr++) {
        int r = r0 + rr;
        int gr = rowBase + r;
        float tv[8];
#pragma unroll
        for (int j = 0; j < 8; j++) {
            int cc = lane + 32 * j;
            tv[j] = fmaxf(Ts[r * LDT + cc] + sb1[cc], 0.f);
        }
        float o[A_DIM];
#pragma unroll
        for (int a = 0; a < A_DIM; a++) {
            float p = 0.f;
#pragma unroll
            for (int j = 0; j < 8; j++)
                p = fmaf(tv[j], sW2[(lane + 32 * j) * A_DIM + a], p);
#pragma unroll
            for (int off = 16; off; off >>= 1) p += __shfl_xor_sync(0xffffffffu, p, off);
            o[a] = p;
        }
        if (lane == 0 && gr < N_NODES) {
#pragma unroll
            for (int a = 0; a < A_DIM; a++)
                out[(size_t)gr * A_DIM + a] = o[a] + sb2[a];
        }
    }
}

// ---------------- launcher ----------------
extern "C" void kernel_launch(void* const* d_in, const int* in_sizes, int n_in,
                              void* d_out, int out_size) {
    const float* x     = (const float*)d_in[0];
    const void*  ei    = d_in[1];
    const float* W_enc = (const float*)d_in[2];
    const float* b_enc = (const float*)d_in[3];
    const float* W_gcn = (const float*)d_in[4];
    const float* b_gcn = (const float*)d_in[5];
    const float* W1    = (const float*)d_in[6];
    const float* b1    = (const float*)d_in[7];
    const float* W2    = (const float*)d_in[8];
    const float* b2    = (const float*)d_in[9];
    float* out = (float*)d_out;

    __half* w116 = nullptr; __half* wg16 = nullptr;
    cudaGetSymbolAddress((void**)&w116, g_W116);
    cudaGetSymbolAddress((void**)&wg16, g_Wg16);

    static cudaStream_t s2 = nullptr;
    static cudaEvent_t evF = nullptr, evFill = nullptr, evDone = nullptr;
    static cudaEvent_t evAgg[N_CHUNK];
    if (!s2) {
        cudaStreamCreateWithFlags(&s2, cudaStreamNonBlocking);
        cudaEventCreateWithFlags(&evF,    cudaEventDisableTiming);
        cudaEventCreateWithFlags(&evFill, cudaEventDisableTiming);
        cudaEventCreateWithFlags(&evDone, cudaEventDisableTiming);
        for (int c = 0; c < N_CHUNK; c++)
            cudaEventCreateWithFlags(&evAgg[c], cudaEventDisableTiming);
        cudaFuncSetAttribute(k_enc,   cudaFuncAttributeMaxDynamicSharedMemorySize, 43008 * 4);
        cudaFuncSetAttribute(k_w1out, cudaFuncAttributeMaxDynamicSharedMemorySize, 33792 * 4);
    }

    // fork: CSR build on s2
    cudaEventRecord(evF, 0);
    cudaStreamWaitEvent(s2, evF, 0);
    k_detect<<<1, 32, 0, s2>>>(ei);
    k_zero_deg<<<cdiv(N_NODES, 256), 256, 0, s2>>>();
    k_hist<<<cdiv(N_EDGES / 2, 256), 256, 0, s2>>>(ei);
    k_scan1<<<NBLK_SCAN, 1024, 0, s2>>>();
    k_scan2<<<1, 128, 0, s2>>>();
    k_scan3<<<NBLK_SCAN, 1024, 0, s2>>>();
    k_fill<<<cdiv(N_EDGES / 4, 256), 256, 0, s2>>>(ei);
    cudaEventRecord(evFill, s2);

    // main: weight converts + encoder (overlaps CSR build)
    k_cvt16<<<cdiv(HQ * H / 4, 256), 256>>>(W1, w116, HQ * H / 4);
    k_cvt16<<<cdiv(H * H / 4, 256), 256>>>(W_gcn, wg16, H * H / 4);
    k_enc<<<N_PAD / 128, 256, 43008 * 4>>>(x, W_enc, b_enc);

    // join for aggregation (needs CSR + dinv + xw16)
    cudaStreamWaitEvent(0, evFill, 0);

    // pipelined agg (main) -> w1out (s2) per chunk
    for (int c = 0; c < N_CHUNK; c++) {
        int nodeBase  = CH_TILE_BASE[c] * 128;
        int nodeCount = CH_TILES[c] * 128;
        k_agg<<<cdiv(nodeCount / 2 * 32, 256), 256>>>(b_gcn, nodeBase, nodeCount);
        cudaEventRecord(evAgg[c], 0);
        cudaStreamWaitEvent(s2, evAgg[c], 0);
        k_w1out<<<CH_TILES[c], 512, 33792 * 4, s2>>>(b1, W2, b2, out, CH_TILE_BASE[c]);
    }
    cudaEventRecord(evDone, s2);
    cudaStreamWaitEvent(0, evDone, 0);
}

// round 9
// speedup vs baseline: 1.2062x; 1.2062x over previous
#include <cuda_runtime.h>
#include <cuda_fp16.h>
#include <mma.h>
#include <cstdint>

using namespace nvcuda;

#define N_NODES 100000
#define N_PAD   100096   // 782 * 128
#define N_EDGES 3200000
#define H 128
#define HQ 256
#define A_DIM 10
#define NBLK_SCAN 98

static inline int cdiv(int a, int b) { return (a + b - 1) / b; }

// ---------------- scratch ----------------
__device__ __half g_x16[(size_t)N_PAD * H];   // fp16 copy of x
__device__ __half g_xw16[(size_t)N_PAD * H];  // fp16 relu(x@We+be)@Wg (UNscaled)
__device__ __half g_h216[(size_t)N_PAD * H];  // fp16 relu(gcn agg)
__device__ __half g_W116[HQ * H];             // fp16 W1 [128,256]
__device__ __half g_Wg16[H * H];              // fp16 W_gcn [128,128]
__device__ __half g_We16[H * H];              // fp16 W_enc [128,128]
__device__ float  g_dinv[N_NODES];
__device__ int    g_deg[N_NODES];
__device__ int    g_rowptr[N_NODES + 1];
__device__ int    g_csrc[N_EDGES];
__device__ int    g_dst32[N_EDGES];
__device__ unsigned short g_rank[N_EDGES];
__device__ int    g_is32;
__device__ int    g_bsum[NBLK_SCAN];
__device__ int    g_boff[NBLK_SCAN];

// ---------------- cp.async helpers ----------------
__device__ __forceinline__ void cp16(void* s, const void* g, bool p) {
    uint32_t sa = (uint32_t)__cvta_generic_to_shared(s);
    int sz = p ? 16 : 0;
    asm volatile("cp.async.cg.shared.global [%0], [%1], 16, %2;\n"
                 :: "r"(sa), "l"(g), "r"(sz));
}
__device__ __forceinline__ void cp_commit() {
    asm volatile("cp.async.commit_group;\n");
}
template <int NN>
__device__ __forceinline__ void cp_wait() {
    asm volatile("cp.async.wait_group %0;\n" :: "n"(NN));
}

// ---------------- generic fp32 -> fp16 convert ----------------
__global__ void k_cvt16(const float* __restrict__ src, __half* __restrict__ dst, int n4) {
    int i = blockIdx.x * blockDim.x + threadIdx.x;
    if (i >= n4) return;
    float4 v = *(const float4*)&src[i * 4];
    __half2 h0 = __floats2half2_rn(v.x, v.y);
    __half2 h1 = __floats2half2_rn(v.z, v.w);
    uint2 u;
    u.x = *(uint32_t*)&h0;
    u.y = *(uint32_t*)&h1;
    *(uint2*)&dst[i * 4] = u;
}

// ---------------- edge dtype detect ----------------
__global__ void k_detect(const void* ei) {
    if (threadIdx.x == 0 && blockIdx.x == 0) {
        const long long* p = (const long long*)ei;
        int is32 = 0;
        for (int i = 0; i < 64; i++) {
            long long v = p[i];
            if (v < 0 || v >= (long long)N_NODES) { is32 = 1; break; }
        }
        g_is32 = is32;
    }
}

__global__ void k_zero_deg() {
    int i = blockIdx.x * blockDim.x + threadIdx.x;
    if (i < N_NODES) g_deg[i] = 0;
}

// histogram over dst half; cache dst as int32 + per-edge rank (atomicAdd old value)
__global__ void k_hist(const void* ei) {
    int i = blockIdx.x * blockDim.x + threadIdx.x;   // 2 edges/thread
    int base = i * 2;
    if (base >= N_EDGES) return;
    int v0, v1;
    if (g_is32) {
        int2 p = ((const int2*)ei)[N_EDGES / 2 + i];
        v0 = p.x; v1 = p.y;
    } else {
        longlong2 p = ((const longlong2*)ei)[N_EDGES / 2 + i];
        v0 = (int)p.x; v1 = (int)p.y;
    }
    *(int2*)&g_dst32[base] = make_int2(v0, v1);
    int r0 = atomicAdd(&g_deg[v0], 1);
    int r1 = atomicAdd(&g_deg[v1], 1);
    g_rank[base]     = (unsigned short)r0;
    g_rank[base + 1] = (unsigned short)r1;
}

// ---------- 3-phase scan ----------
__global__ void k_scan1() {
    __shared__ int warpsum[32];
    int tid = threadIdx.x, lane = tid & 31, wid = tid >> 5;
    int i = blockIdx.x * 1024 + tid;
    int v = (i < N_NODES) ? g_deg[i] : 0;
    int x = v;
#pragma unroll
    for (int off = 1; off < 32; off <<= 1) {
        int y = __shfl_up_sync(0xffffffffu, x, off);
        if (lane >= off) x += y;
    }
    if (lane == 31) warpsum[wid] = x;
    __syncthreads();
    if (wid == 0) {
        int w = warpsum[lane];
#pragma unroll
        for (int off = 1; off < 32; off <<= 1) {
            int y = __shfl_up_sync(0xffffffffu, w, off);
            if (lane >= off) w += y;
        }
        warpsum[lane] = w;
    }
    __syncthreads();
    int incl = x + (wid > 0 ? warpsum[wid - 1] : 0);
    if (i < N_NODES) {
        g_rowptr[i] = incl - v;
        g_dinv[i] = rsqrtf((float)(v + 1));
    }
    if (tid == 1023) g_bsum[blockIdx.x] = incl;
}

__global__ void k_scan2() {
    __shared__ int s[128];
    int t = threadIdx.x;
    s[t] = (t < NBLK_SCAN) ? g_bsum[t] : 0;
    __syncthreads();
    for (int off = 1; off < 128; off <<= 1) {
        int v = (t >= off) ? s[t - off] : 0;
        __syncthreads();
        s[t] += v;
        __syncthreads();
    }
    if (t < NBLK_SCAN) g_boff[t] = (t > 0) ? s[t - 1] : 0;
    if (t == 0) g_rowptr[N_NODES] = s[NBLK_SCAN - 1];
}

__global__ void k_scan3() {
    int i = blockIdx.x * 1024 + threadIdx.x;
    if (i >= N_NODES) return;
    g_rowptr[i] += g_boff[blockIdx.x];
}

// fill CSR: atomic-free, pos = rowptr[dst] + rank
__global__ void k_fill(const void* ei) {
    int i = blockIdx.x * blockDim.x + threadIdx.x;   // 4 edges/thread
    int base = i * 4;
    if (base >= N_EDGES) return;
    int s0, s1, s2, s3;
    if (g_is32) {
        int4 sv = ((const int4*)ei)[i];
        s0 = sv.x; s1 = sv.y; s2 = sv.z; s3 = sv.w;
    } else {
        longlong2 a = ((const longlong2*)ei)[i * 2];
        longlong2 b = ((const longlong2*)ei)[i * 2 + 1];
        s0 = (int)a.x; s1 = (int)a.y; s2 = (int)b.x; s3 = (int)b.y;
    }
    int4 d = *(const int4*)&g_dst32[base];
    ushort4 rk = *(const ushort4*)&g_rank[base];
    g_csrc[g_rowptr[d.x] + rk.x] = s0;
    g_csrc[g_rowptr[d.y] + rk.y] = s1;
    g_csrc[g_rowptr[d.z] + rk.z] = s2;
    g_csrc[g_rowptr[d.w] + rk.w] = s3;
}

// ========== all-fp16 fused encoder + GCN-weight GEMM, single-shot ==========
// xw16 = fp16( relu(x16 @ We16 + b_enc) @ Wg16 )
#define LDH 136       // halves
#define LDW 132       // floats (Ts)

__global__ __launch_bounds__(256) void k_enc(const float* __restrict__ b_enc)
{
    extern __shared__ float pool[];
    __half* Hh  = (__half*)pool;                 // 128*136 h = 34816 B
    __half* Wgh = (__half*)(pool + 8704);        // 128*136 h
    __half* Ah  = (__half*)(pool + 17408);       // 128*136 h
    __half* Weh = (__half*)(pool + 26112);       // 128*136 h
    float*  Ts  = pool + 17408;                  // 128*132 f (aliases Ah+Weh)
    __shared__ float sbe[128];

    const int tid = threadIdx.x;
    const int wid = tid >> 5;
    const int wm = wid & 3, wn = wid >> 2;
    const int rowBase = blockIdx.x * 128;

    if (tid < 128) sbe[tid] = b_enc[tid];

    // single-shot staging: A (guarded), W_enc, W_gcn — each 128x128 h = 2048 x 16B
#pragma unroll
    for (int i = 0; i < 8; i++) {
        int slot = tid + i * 256;
        int r = slot >> 4, c8 = (slot & 15) * 8;
        int gr = rowBase + r;
        cp16(&Ah[r * LDH + c8],  &g_x16[(size_t)gr * 128 + c8], gr < N_NODES);
        cp16(&Weh[r * LDH + c8], &g_We16[r * 128 + c8], true);
        cp16(&Wgh[r * LDH + c8], &g_Wg16[r * 128 + c8], true);
    }
    cp_commit();
    cp_wait<0>();
    __syncthreads();

    // ---- stage 1: fp16, acc1 = x @ W_enc ----
    wmma::fragment<wmma::accumulator, 16, 16, 16, float> acc[2][4];
#pragma unroll
    for (int mt = 0; mt < 2; mt++)
#pragma unroll
        for (int nt = 0; nt < 4; nt++) wmma::fill_fragment(acc[mt][nt], 0.f);

#pragma unroll
    for (int ks = 0; ks < 8; ks++) {
        int k = ks * 16;
        wmma::fragment<wmma::matrix_a, 16, 16, 16, __half, wmma::row_major> af[2];
        wmma::fragment<wmma::matrix_b, 16, 16, 16, __half, wmma::row_major> bf[4];
#pragma unroll
        for (int mt = 0; mt < 2; mt++)
            wmma::load_matrix_sync(af[mt], &Ah[(wm * 32 + mt * 16) * LDH + k], LDH);
#pragma unroll
        for (int nt = 0; nt < 4; nt++)
            wmma::load_matrix_sync(bf[nt], &Weh[k * LDH + wn * 64 + nt * 16], LDH);
#pragma unroll
        for (int mt = 0; mt < 2; mt++)
#pragma unroll
            for (int nt = 0; nt < 4; nt++)
                wmma::mma_sync(acc[mt][nt], af[mt], bf[nt], acc[mt][nt]);
    }
    __syncthreads();   // all reads of Ah/Weh done before Ts alias write

#pragma unroll
    for (int mt = 0; mt < 2; mt++)
#pragma unroll
        for (int nt = 0; nt < 4; nt++)
            wmma::store_matrix_sync(&Ts[(wm * 32 + mt * 16) * LDW + wn * 64 + nt * 16],
                                    acc[mt][nt], LDW, wmma::mem_row_major);
    __syncthreads();

    // bias + relu + fp16 pack: Ts -> Hh
#pragma unroll
    for (int i = 0; i < 16; i++) {
        int slot = tid + i * 256;
        int r = slot >> 5, c4 = (slot & 31) * 4;
        float4 v = *(float4*)&Ts[r * LDW + c4];
        __half2 h0 = __floats2half2_rn(fmaxf(v.x + sbe[c4 + 0], 0.f),
                                       fmaxf(v.y + sbe[c4 + 1], 0.f));
        __half2 h1 = __floats2half2_rn(fmaxf(v.z + sbe[c4 + 2], 0.f),
                                       fmaxf(v.w + sbe[c4 + 3], 0.f));
        uint2 u;
        u.x = *(uint32_t*)&h0;
        u.y = *(uint32_t*)&h1;
        *(uint2*)&Hh[r * LDH + c4] = u;
    }
    __syncthreads();

    // ---- stage 2: fp16, acc2 = relu(h1) @ W_gcn ----
#pragma unroll
    for (int mt = 0; mt < 2; mt++)
#pragma unroll
        for (int nt = 0; nt < 4; nt++) wmma::fill_fragment(acc[mt][nt], 0.f);

#pragma unroll
    for (int ks = 0; ks < 8; ks++) {
        int k = ks * 16;
        wmma::fragment<wmma::matrix_a, 16, 16, 16, __half, wmma::row_major> af[2];
        wmma::fragment<wmma::matrix_b, 16, 16, 16, __half, wmma::row_major> bf[4];
#pragma unroll
        for (int mt = 0; mt < 2; mt++)
            wmma::load_matrix_sync(af[mt], &Hh[(wm * 32 + mt * 16) * LDH + k], LDH);
#pragma unroll
        for (int nt = 0; nt < 4; nt++)
            wmma::load_matrix_sync(bf[nt], &Wgh[k * LDH + wn * 64 + nt * 16], LDH);
#pragma unroll
        for (int mt = 0; mt < 2; mt++)
#pragma unroll
            for (int nt = 0; nt < 4; nt++)
                wmma::mma_sync(acc[mt][nt], af[mt], bf[nt], acc[mt][nt]);
    }
    __syncthreads();

#pragma unroll
    for (int mt = 0; mt < 2; mt++)
#pragma unroll
        for (int nt = 0; nt < 4; nt++)
            wmma::store_matrix_sync(&Ts[(wm * 32 + mt * 16) * LDW + wn * 64 + nt * 16],
                                    acc[mt][nt], LDW, wmma::mem_row_major);
    __syncthreads();

    // fp16 pack + store
#pragma unroll
    for (int i = 0; i < 16; i++) {
        int slot = tid + i * 256;
        int r = slot >> 5, c4 = (slot & 31) * 4;
        int gr = rowBase + r;
        float4 v = *(float4*)&Ts[r * LDW + c4];
        __half2 h0 = __floats2half2_rn(v.x, v.y);
        __half2 h1 = __floats2half2_rn(v.z, v.w);
        uint2 u;
        u.x = *(uint32_t*)&h0;
        u.y = *(uint32_t*)&h1;
        *(uint2*)&g_xw16[(size_t)gr * 128 + c4] = u;
    }
}

// ------- GCN aggregation: 2 nodes/warp, 16 lanes x 16B per row -------
__device__ __forceinline__ void fma8(float* acc, float c, uint4 u) {
    __half2* h = (__half2*)&u;
#pragma unroll
    for (int q = 0; q < 4; q++) {
        float2 f = __half22float2(h[q]);
        acc[q * 2]     = fmaf(c, f.x, acc[q * 2]);
        acc[q * 2 + 1] = fmaf(c, f.y, acc[q * 2 + 1]);
    }
}

__global__ void k_agg(const float* __restrict__ b_gcn) {
    int warpId = (blockIdx.x * blockDim.x + threadIdx.x) >> 5;
    int lane = threadIdx.x & 31;
    int sub = lane >> 4;
    int l16 = lane & 15;
    unsigned hmask = sub ? 0xFFFF0000u : 0x0000FFFFu;
    int gw = warpId * 2 + sub;
    if (gw >= N_NODES) return;

    int beg = g_rowptr[gw];
    int end = g_rowptr[gw + 1];

    float acc[8];
#pragma unroll
    for (int q = 0; q < 8; q++) acc[q] = 0.f;

    const int colh = l16 * 8;

    for (int base = beg; base < end; base += 16) {
        int e = base + l16;
        int s = (e < end) ? g_csrc[e] : 0;
        int cnt = min(16, end - base);
        if (cnt == 16) {
#pragma unroll
            for (int j = 0; j < 16; j++) {
                int sj = __shfl_sync(hmask, s, sub * 16 + j);
                float c = g_dinv[sj];
                uint4 u = *(const uint4*)&g_xw16[(size_t)sj * 128 + colh];
                fma8(acc, c, u);
            }
        } else {
            for (int j = 0; j < cnt; j++) {
                int sj = __shfl_sync(hmask, s, sub * 16 + j);
                float c = g_dinv[sj];
                uint4 u = *(const uint4*)&g_xw16[(size_t)sj * 128 + colh];
                fma8(acc, c, u);
            }
        }
    }

    float di = g_dinv[gw];
    {
        uint4 u = *(const uint4*)&g_xw16[(size_t)gw * 128 + colh];
        fma8(acc, di, u);
    }

    float4 b0 = *(const float4*)&b_gcn[colh];
    float4 b1 = *(const float4*)&b_gcn[colh + 4];
    float bb[8] = {b0.x, b0.y, b0.z, b0.w, b1.x, b1.y, b1.z, b1.w};
    __half2 ho[4];
#pragma unroll
    for (int q = 0; q < 4; q++) {
        float ox = fmaxf(fmaf(di, acc[q * 2],     bb[q * 2]),     0.f);
        float oy = fmaxf(fmaf(di, acc[q * 2 + 1], bb[q * 2 + 1]), 0.f);
        ho[q] = __floats2half2_rn(ox, oy);
    }
    *(uint4*)&g_h216[(size_t)gw * 128 + colh] = *(uint4*)ho;
}

// ========== fused MLP head (fp16 wmma, single K stage) ==========
#define LDA2 136     // halves
#define LDB2 264     // halves
#define LDT 264      // floats

__global__ __launch_bounds__(512) void k_w1out(
    const float* __restrict__ b1, const float* __restrict__ W2,
    const float* __restrict__ b2, float* __restrict__ out)
{
    extern __shared__ float pool[];
    __half* As = (__half*)pool;                 // 128*136 h
    __half* Bs = (__half*)pool + 128 * LDA2;    // 128*264 h
    float*  Ts = pool;                          // alias: 128*264 f
    __shared__ float sW2[HQ * A_DIM];
    __shared__ float sb1[HQ];
    __shared__ float sb2[A_DIM];

    const int tid = threadIdx.x;
    const int wid = tid >> 5, lane = tid & 31;
    const int wm = wid & 3, wn = wid >> 2;
    const int rowBase = blockIdx.x * 128;

    for (int j = tid; j < HQ * A_DIM; j += 512) sW2[j] = W2[j];
    for (int j = tid; j < HQ; j += 512) sb1[j] = b1[j];
    if (tid < A_DIM) sb2[tid] = b2[tid];

#pragma unroll
    for (int i = 0; i < 4; i++) {
        int slot = tid + i * 512;
        int r = slot >> 4, c8 = (slot & 15) * 8;
        cp16(&As[r * LDA2 + c8], &g_h216[(size_t)(rowBase + r) * 128 + c8], true);
    }
#pragma unroll
    for (int i = 0; i < 8; i++) {
        int slot = tid + i * 512;
        int r = slot >> 5, c8 = (slot & 31) * 8;
        cp16(&Bs[r * LDB2 + c8], &g_W116[(size_t)r * 256 + c8], true);
    }
    cp_commit();
    cp_wait<0>();
    __syncthreads();

    wmma::fragment<wmma::accumulator, 16, 16, 16, float> acc[2][4];
#pragma unroll
    for (int mt = 0; mt < 2; mt++)
#pragma unroll
        for (int nt = 0; nt < 4; nt++) wmma::fill_fragment(acc[mt][nt], 0.f);

#pragma unroll
    for (int ks = 0; ks < 8; ks++) {
        int k = ks * 16;
        wmma::fragment<wmma::matrix_a, 16, 16, 16, __half, wmma::row_major> af[2];
        wmma::fragment<wmma::matrix_b, 16, 16, 16, __half, wmma::row_major> bf[4];
#pragma unroll
        for (int mt = 0; mt < 2; mt++)
            wmma::load_matrix_sync(af[mt], &As[(wm * 32 + mt * 16) * LDA2 + k], LDA2);
#pragma unroll
        for (int nt = 0; nt < 4; nt++)
            wmma::load_matrix_sync(bf[nt], &Bs[k * LDB2 + wn * 64 + nt * 16], LDB2);
#pragma unroll
        for (int mt = 0; mt < 2; mt++)
#pragma unroll
            for (int nt = 0; nt < 4; nt++)
                wmma::mma_sync(acc[mt][nt], af[mt], bf[nt], acc[mt][nt]);
    }
    __syncthreads();

#pragma unroll
    for (int mt = 0; mt < 2; mt++)
#pragma unroll
        for (int nt = 0; nt < 4; nt++)
            wmma::store_matrix_sync(&Ts[(wm * 32 + mt * 16) * LDT + wn * 64 + nt * 16],
                                    acc[mt][nt], LDT, wmma::mem_row_major);
    __syncthreads();

    int r0 = wid * 8;
#pragma unroll
    for (int rr = 0; rr < 8; rr++) {
        int r = r0 + rr;
        int gr = rowBase + r;
        float tv[8];
#pragma unroll
        for (int j = 0; j < 8; j++) {
            int cc = lane + 32 * j;
            tv[j] = fmaxf(Ts[r * LDT + cc] + sb1[cc], 0.f);
        }
        float o[A_DIM];
#pragma unroll
        for (int a = 0; a < A_DIM; a++) {
            float p = 0.f;
#pragma unroll
            for (int j = 0; j < 8; j++)
                p = fmaf(tv[j], sW2[(lane + 32 * j) * A_DIM + a], p);
#pragma unroll
            for (int off = 16; off; off >>= 1) p += __shfl_xor_sync(0xffffffffu, p, off);
            o[a] = p;
        }
        if (lane == 0 && gr < N_NODES) {
#pragma unroll
            for (int a = 0; a < A_DIM; a++)
                out[(size_t)gr * A_DIM + a] = o[a] + sb2[a];
        }
    }
}

// ---------------- launcher ----------------
extern "C" void kernel_launch(void* const* d_in, const int* in_sizes, int n_in,
                              void* d_out, int out_size) {
    const float* x     = (const float*)d_in[0];
    const void*  ei    = d_in[1];
    const float* W_enc = (const float*)d_in[2];
    const float* b_enc = (const float*)d_in[3];
    const float* W_gcn = (const float*)d_in[4];
    const float* b_gcn = (const float*)d_in[5];
    const float* W1    = (const float*)d_in[6];
    const float* b1    = (const float*)d_in[7];
    const float* W2    = (const float*)d_in[8];
    const float* b2    = (const float*)d_in[9];
    float* out = (float*)d_out;

    __half *x16 = nullptr, *w116 = nullptr, *wg16 = nullptr, *we16 = nullptr;
    cudaGetSymbolAddress((void**)&x16,  g_x16);
    cudaGetSymbolAddress((void**)&w116, g_W116);
    cudaGetSymbolAddress((void**)&wg16, g_Wg16);
    cudaGetSymbolAddress((void**)&we16, g_We16);

    static cudaStream_t s2 = nullptr;
    static cudaEvent_t evF = nullptr, evFill = nullptr;
    if (!s2) {
        cudaStreamCreateWithFlags(&s2, cudaStreamNonBlocking);
        cudaEventCreateWithFlags(&evF,    cudaEventDisableTiming);
        cudaEventCreateWithFlags(&evFill, cudaEventDisableTiming);
        cudaFuncSetAttribute(k_enc,   cudaFuncAttributeMaxDynamicSharedMemorySize, 139264);
        cudaFuncSetAttribute(k_w1out, cudaFuncAttributeMaxDynamicSharedMemorySize, 135168);
    }

    // fork: CSR build on s2
    cudaEventRecord(evF, 0);
    cudaStreamWaitEvent(s2, evF, 0);
    k_detect<<<1, 32, 0, s2>>>(ei);
    k_zero_deg<<<cdiv(N_NODES, 256), 256, 0, s2>>>();
    k_hist<<<cdiv(N_EDGES / 2, 256), 256, 0, s2>>>(ei);
    k_scan1<<<NBLK_SCAN, 1024, 0, s2>>>();
    k_scan2<<<1, 128, 0, s2>>>();
    k_scan3<<<NBLK_SCAN, 1024, 0, s2>>>();
    k_fill<<<cdiv(N_EDGES / 4, 256), 256, 0, s2>>>(ei);
    cudaEventRecord(evFill, s2);

    // main: converts + encoder (overlap CSR build)
    k_cvt16<<<cdiv(N_NODES * H / 4, 256), 256>>>(x, x16, N_NODES * H / 4);
    k_cvt16<<<cdiv(HQ * H / 4, 256), 256>>>(W1, w116, HQ * H / 4);
    k_cvt16<<<cdiv(H * H / 4, 256), 256>>>(W_gcn, wg16, H * H / 4);
    k_cvt16<<<cdiv(H * H / 4, 256), 256>>>(W_enc, we16, H * H / 4);
    k_enc<<<N_PAD / 128, 256, 139264>>>(b_enc);

    // join: aggregation needs CSR + dinv + xw16; then MLP head
    cudaStreamWaitEvent(0, evFill, 0);
    k_agg<<<cdiv(N_NODES / 2 * 32, 256), 256>>>(b_gcn);
    k_w1out<<<N_PAD / 128, 512, 135168>>>(b1, W2, b2, out);
}